// round 10
// baseline (speedup 1.0000x reference)
#include <cuda_runtime.h>
#include <cuda_bf16.h>

#define N_NODES 50000
#define D 128
#define N_EDGES 800000
#define N_EVAL 100000

// ---------------- scratch (device globals; no allocation allowed) ----------
__device__ float g_bufA[N_NODES * D];   // h1 (gemm1 out), later z2
__device__ float g_bufB[N_NODES * D];   // z1
__device__ float g_bufZ[N_NODES * D];   // h2
__device__ float g_dinv[N_NODES];
__device__ int   g_cnt[N_NODES];        // zeroed by k_scan each run
__device__ int   g_rowptr[N_NODES + 1];
__device__ int   g_slot[N_EDGES];       // per-edge slot from count phase
__device__ int2  g_csr[N_EDGES];        // interleaved {src, norm_bits}

// ---------------- f32x2 helpers --------------------------------------------
__device__ __forceinline__ void ffma2(unsigned long long& d, unsigned long long a,
                                      unsigned long long b) {
    asm("fma.rn.f32x2 %0, %1, %2, %0;" : "+l"(d) : "l"(a), "l"(b));
}
__device__ __forceinline__ unsigned long long pack2(float x) {
    unsigned long long r;
    asm("mov.b64 %0, {%1, %1};" : "=l"(r) : "f"(x));
    return r;
}
__device__ __forceinline__ void unpack2(float& lo, float& hi, unsigned long long v) {
    asm("mov.b64 {%0, %1}, %2;" : "=f"(lo), "=f"(hi) : "l"(v));
}

// ---------------- GEMM device body (f32x2 FFMA2) ---------------------------
#define TM 64
#define KC 32
#define XT_PITCH 66
#define GEMM_GRID ((N_NODES + TM - 1) / TM)     // 782

struct GemmSmem {
    float Xt[KC][XT_PITCH];
    float Ws[KC][D];
};

__device__ __forceinline__ void gemm_body(GemmSmem& s,
                                          const float* __restrict__ X,
                                          const float* __restrict__ W,
                                          float* __restrict__ H, int bid) {
    int row0 = bid * TM;
    int tid = threadIdx.x;                // 256 threads
    int tx = tid & 31;
    int ty = tid >> 5;
    unsigned long long acc[4][4];
    #pragma unroll
    for (int p = 0; p < 4; p++)
        #pragma unroll
        for (int c = 0; c < 4; c++) acc[p][c] = 0ull;

    for (int k0 = 0; k0 < D; k0 += KC) {
        for (int i = tid; i < (TM * KC) / 4; i += 256) {
            int r = i >> 3;
            int c4 = i & 7;
            int gr = row0 + r;
            float4 v = (gr < N_NODES) ? *(const float4*)(X + gr * D + k0 + c4 * 4)
                                      : make_float4(0.f, 0.f, 0.f, 0.f);
            s.Xt[c4 * 4 + 0][r] = v.x;
            s.Xt[c4 * 4 + 1][r] = v.y;
            s.Xt[c4 * 4 + 2][r] = v.z;
            s.Xt[c4 * 4 + 3][r] = v.w;
        }
        for (int i = tid; i < (KC * D) / 4; i += 256) {
            int r = i >> 5, c4 = i & 31;
            *(float4*)&s.Ws[r][c4 * 4] = *(const float4*)(W + (k0 + r) * D + c4 * 4);
        }
        __syncthreads();
        #pragma unroll
        for (int k = 0; k < KC; k++) {
            float4 b4 = *(const float4*)&s.Ws[k][tx * 4];
            unsigned long long b0 = pack2(b4.x), b1 = pack2(b4.y);
            unsigned long long b2 = pack2(b4.z), b3 = pack2(b4.w);
            #pragma unroll
            for (int p = 0; p < 4; p++) {
                unsigned long long a =
                    *(const unsigned long long*)&s.Xt[k][ty * 8 + 2 * p];
                ffma2(acc[p][0], a, b0);
                ffma2(acc[p][1], a, b1);
                ffma2(acc[p][2], a, b2);
                ffma2(acc[p][3], a, b3);
            }
        }
        __syncthreads();
    }
    #pragma unroll
    for (int p = 0; p < 4; p++) {
        float lo0, hi0, lo1, hi1, lo2, hi2, lo3, hi3;
        unpack2(lo0, hi0, acc[p][0]);
        unpack2(lo1, hi1, acc[p][1]);
        unpack2(lo2, hi2, acc[p][2]);
        unpack2(lo3, hi3, acc[p][3]);
        int gr0 = row0 + ty * 8 + 2 * p;
        if (gr0 < N_NODES) {
            float4 v = {lo0, lo1, lo2, lo3};
            *(float4*)(H + gr0 * D + tx * 4) = v;
        }
        if (gr0 + 1 < N_NODES) {
            float4 v = {hi0, hi1, hi2, hi3};
            *(float4*)(H + (gr0 + 1) * D + tx * 4) = v;
        }
    }
}

// ---------------- Fused: gemm1 (even blocks) + count+slot (odd blocks) -----
__global__ void k_gemm1_count(const float* __restrict__ X, const float* __restrict__ W,
                              float* __restrict__ H, const int* __restrict__ dst) {
    __shared__ GemmSmem s;
    int bid = blockIdx.x >> 1;
    if ((blockIdx.x & 1) == 0) {
        gemm_body(s, X, W, H, bid);
    } else {
        int base = (bid * 256 + threadIdx.x) * 4;
        if (base + 3 < N_EDGES) {
            int4 d4 = *(const int4*)(dst + base);
            int4 s4;
            s4.x = atomicAdd(&g_cnt[d4.x], 1);
            s4.y = atomicAdd(&g_cnt[d4.y], 1);
            s4.z = atomicAdd(&g_cnt[d4.z], 1);
            s4.w = atomicAdd(&g_cnt[d4.w], 1);
            *(int4*)(g_slot + base) = s4;
        } else {
            for (int e = base; e < N_EDGES; e++)
                g_slot[e] = atomicAdd(&g_cnt[dst[e]], 1);
        }
    }
}

// ---------------- Single-kernel scan (PDL-aware) ---------------------------
#define SCAN_CHUNK 512
#define NB_SCAN ((N_NODES + SCAN_CHUNK - 1) / SCAN_CHUNK)   // 98
__global__ void k_scan() {
    __shared__ int tmp[SCAN_CHUNK];
    int b = blockIdx.x, t = threadIdx.x;

    cudaGridDependencySynchronize();      // wait for counts (PDL)

    int part = 0;
    for (int i = t; i < b * SCAN_CHUNK; i += SCAN_CHUNK) part += g_cnt[i];
    tmp[t] = part;
    __syncthreads();
    #pragma unroll
    for (int off = SCAN_CHUNK / 2; off > 0; off >>= 1) {
        if (t < off) tmp[t] += tmp[t + off];
        __syncthreads();
    }
    int base = tmp[0];
    __syncthreads();

    int i = b * SCAN_CHUNK + t;
    int v = (i < N_NODES) ? g_cnt[i] : 0;
    tmp[t] = v;
    __syncthreads();
    #pragma unroll
    for (int off = 1; off < SCAN_CHUNK; off <<= 1) {
        int x = (t >= off) ? tmp[t - off] : 0;
        __syncthreads();
        tmp[t] += x;
        __syncthreads();
    }
    if (i < N_NODES) {
        g_rowptr[i + 1] = base + tmp[t];
        if (i == 0) g_rowptr[0] = 0;
        g_dinv[i] = rsqrtf((float)v + 1.0f);
        g_cnt[i] = 0;
    }
}

// ---------------- Fill (atomic-free; prologue loads inputs pre-sync) -------
__global__ void k_fill(const int* __restrict__ src, const int* __restrict__ dst) {
    int base = (blockIdx.x * 256 + threadIdx.x) * 4;
    if (base + 3 < N_EDGES) {
        // prologue: harness inputs + slot (written 2 kernels back) —
        // slot still needs the sync, so split: inputs first.
        int4 s4 = *(const int4*)(src + base);
        int4 d4 = *(const int4*)(dst + base);
        cudaGridDependencySynchronize();  // wait for scan (rowptr/dinv) + slots
        int4 sl = *(const int4*)(g_slot + base);
        #pragma unroll
        for (int j = 0; j < 4; j++) {
            int s = (&s4.x)[j], d = (&d4.x)[j], slot = (&sl.x)[j];
            float nm = g_dinv[s] * g_dinv[d];
            g_csr[g_rowptr[d] + slot] = make_int2(s, __float_as_int(nm));
        }
    } else {
        cudaGridDependencySynchronize();
        for (int e = base; e < N_EDGES; e++) {
            int s = src[e], d = dst[e];
            float nm = g_dinv[s] * g_dinv[d];
            g_csr[g_rowptr[d] + g_slot[e]] = make_int2(s, __float_as_int(nm));
        }
    }
}

// ---------------- GEMM standalone (layer 2, PDL-aware) ---------------------
__global__ void k_gemm(const float* __restrict__ X, const float* __restrict__ W,
                       float* __restrict__ H) {
    __shared__ GemmSmem s;
    cudaGridDependencySynchronize();      // wait for agg1 (z1)
    gemm_body(s, X, W, H, blockIdx.x);
}

// ---------------- Aggregation (32-reg loop; prologue pre-sync) -------------
__global__ void k_agg(const float* __restrict__ H, const float* __restrict__ bias,
                      float* __restrict__ Z, int relu_out) {
    int node = blockIdx.x * (blockDim.x >> 5) + (threadIdx.x >> 5);
    int lane = threadIdx.x & 31;
    // prologue: bias is a harness input — load before the dependency sync
    float4 b = ((const float4*)bias)[lane];
    cudaGridDependencySynchronize();      // wait for H + csr/rowptr/dinv
    if (node >= N_NODES) return;
    const float4* H4 = (const float4*)H;
    float di = g_dinv[node];
    float sl = di * di;
    float4 acc = H4[node * 32 + lane];
    acc.x *= sl; acc.y *= sl; acc.z *= sl; acc.w *= sl;
    int e0 = g_rowptr[node], e1 = g_rowptr[node + 1];
    #pragma unroll 4
    for (int e = e0; e < e1; e++) {
        int2 pr = g_csr[e];
        float nm = __int_as_float(pr.y);
        float4 v = H4[pr.x * 32 + lane];
        acc.x = fmaf(v.x, nm, acc.x);
        acc.y = fmaf(v.y, nm, acc.y);
        acc.z = fmaf(v.z, nm, acc.z);
        acc.w = fmaf(v.w, nm, acc.w);
    }
    acc.x += b.x; acc.y += b.y; acc.z += b.z; acc.w += b.w;
    if (relu_out) {
        acc.x = fmaxf(acc.x, 0.f); acc.y = fmaxf(acc.y, 0.f);
        acc.z = fmaxf(acc.z, 0.f); acc.w = fmaxf(acc.w, 0.f);
    }
    ((float4*)Z)[node * 32 + lane] = acc;
}

// ---------------- Scores: 4 pairs/warp; index loads pre-sync ---------------
__global__ void k_score2(const float* __restrict__ Z, const int* __restrict__ pos,
                         const int* __restrict__ neg, float* __restrict__ out) {
    int w = blockIdx.x * (blockDim.x >> 5) + (threadIdx.x >> 5);
    int lane = threadIdx.x & 31;
    int i0 = w * 4;
    if (i0 >= 2 * N_EVAL) { cudaGridDependencySynchronize(); return; }
    const int* idx = (i0 < N_EVAL) ? pos : neg;
    int j0 = (i0 < N_EVAL) ? i0 : i0 - N_EVAL;
    // prologue: index gathers are harness inputs — fetch before sync
    int4 a4 = *(const int4*)(idx + j0);
    int4 b4 = *(const int4*)(idx + N_EVAL + j0);
    cudaGridDependencySynchronize();      // wait for z2
    const float4* Z4 = (const float4*)Z;
    float4 va0 = Z4[a4.x * 32 + lane];
    float4 va1 = Z4[a4.y * 32 + lane];
    float4 va2 = Z4[a4.z * 32 + lane];
    float4 va3 = Z4[a4.w * 32 + lane];
    float4 vb0 = Z4[b4.x * 32 + lane];
    float4 vb1 = Z4[b4.y * 32 + lane];
    float4 vb2 = Z4[b4.z * 32 + lane];
    float4 vb3 = Z4[b4.w * 32 + lane];
    float s0 = va0.x * vb0.x + va0.y * vb0.y + va0.z * vb0.z + va0.w * vb0.w;
    float s1 = va1.x * vb1.x + va1.y * vb1.y + va1.z * vb1.z + va1.w * vb1.w;
    float s2 = va2.x * vb2.x + va2.y * vb2.y + va2.z * vb2.z + va2.w * vb2.w;
    float s3 = va3.x * vb3.x + va3.y * vb3.y + va3.z * vb3.z + va3.w * vb3.w;
    #pragma unroll
    for (int off = 16; off; off >>= 1) {
        s0 += __shfl_xor_sync(0xFFFFFFFFu, s0, off);
        s1 += __shfl_xor_sync(0xFFFFFFFFu, s1, off);
        s2 += __shfl_xor_sync(0xFFFFFFFFu, s2, off);
        s3 += __shfl_xor_sync(0xFFFFFFFFu, s3, off);
    }
    if (lane == 0) *(float4*)(out + i0) = make_float4(s0, s1, s2, s3);
}

// ---------------- launch (single stream + PDL edges) -----------------------
template <typename... Args>
static void launch_pdl(void (*kern)(Args...), dim3 grid, dim3 block, Args... args) {
    cudaLaunchConfig_t cfg = {};
    cfg.gridDim = grid;
    cfg.blockDim = block;
    cfg.dynamicSmemBytes = 0;
    cfg.stream = 0;                        // legacy default stream (as <<<>>>)
    cudaLaunchAttribute attr[1];
    attr[0].id = cudaLaunchAttributeProgrammaticStreamSerialization;
    attr[0].val.programmaticStreamSerializationAllowed = 1;
    cfg.attrs = attr;
    cfg.numAttrs = 1;
    cudaLaunchKernelEx(&cfg, kern, args...);
}

extern "C" void kernel_launch(void* const* d_in, const int* in_sizes, int n_in,
                              void* d_out, int out_size) {
    const float* x   = (const float*)d_in[0];
    const float* W1  = (const float*)d_in[1];
    const float* b1  = (const float*)d_in[2];
    const float* W2  = (const float*)d_in[3];
    const float* b2  = (const float*)d_in[4];
    const int* ei    = (const int*)d_in[5];
    const int* pos   = (const int*)d_in[6];
    const int* neg   = (const int*)d_in[7];
    float* out = (float*)d_out;

    const int* src = ei;
    const int* dst = ei + N_EDGES;

    float *bufA, *bufB, *bufZ;
    cudaGetSymbolAddress((void**)&bufA, g_bufA);
    cudaGetSymbolAddress((void**)&bufB, g_bufB);
    cudaGetSymbolAddress((void**)&bufZ, g_bufZ);

    int agg_grid = (N_NODES + 7) / 8;
    int sc_grid = (2 * N_EVAL / 4 + 7) / 8;
    int fill_grid = (N_EDGES / 4 + 255) / 256;

    // (1) gemm1 + count (no predecessor)
    k_gemm1_count<<<2 * GEMM_GRID, 256>>>(x, W1, bufA, dst);
    // (2..7) downstream kernels launch early via PDL, sync inside
    launch_pdl(k_scan, dim3(NB_SCAN), dim3(SCAN_CHUNK));
    launch_pdl(k_fill, dim3(fill_grid), dim3(256), src, dst);
    launch_pdl(k_agg, dim3(agg_grid), dim3(256),
               (const float*)bufA, b1, bufB, 1);
    launch_pdl(k_gemm, dim3(GEMM_GRID), dim3(256),
               (const float*)bufB, W2, bufZ);
    launch_pdl(k_agg, dim3(agg_grid), dim3(256),
               (const float*)bufZ, b2, bufA, 0);
    launch_pdl(k_score2, dim3(sc_grid), dim3(256),
               (const float*)bufA, pos, neg, out);
}